// round 12
// baseline (speedup 1.0000x reference)
#include <cuda_runtime.h>
#include <math.h>

#define N_NODES 4096
#define KDIM    512
#define D_H     64
#define HEADS   8
#define MAXD    192
#define CH      64
#define KSPLIT  8
#define KS      64
#define BM      32
#define ROWBLKS 128
#define GEMM_ITEMS 1024
#define NBLK    296
#define NHALF   592
#define NWARP   2368

typedef unsigned long long ull;

// ---------------- packed f32x2 helpers (Blackwell) ----------------
__device__ __forceinline__ ull pack2(float a) {
    ull r;
    asm("mov.b64 %0, {%1, %1};" : "=l"(r) : "f"(a));
    return r;
}
__device__ __forceinline__ void fma2(ull& d, ull a, ull b) {
    asm("fma.rn.f32x2 %0, %1, %2, %0;" : "+l"(d) : "l"(a), "l"(b));
}
__device__ __forceinline__ void add2(ull& d, ull a) {
    asm("add.rn.f32x2 %0, %0, %1;" : "+l"(d) : "l"(a));
}
__device__ __forceinline__ void unpack2(ull v, float& lo, float& hi) {
    asm("mov.b64 {%0, %1}, %2;" : "=f"(lo), "=f"(hi) : "l"(v));
}

#define HBAR(id) asm volatile("bar.sync %0, 128;" :: "r"(id) : "memory")

// ---------------- scratch ----------------
__device__ float g_x [N_NODES * D_H];
__device__ float g_el[N_NODES * HEADS];
__device__ float g_er[N_NODES * HEADS];
__device__ float g_h1[N_NODES * D_H * HEADS];
__device__ float g_h2[N_NODES * D_H * HEADS];
__device__ float g_part[KSPLIT * N_NODES * D_H];
__device__ int   g_cols[N_NODES * MAXD];
__device__ int   g_deg [N_NODES];
__device__ unsigned g_cnt[ROWBLKS];   // split-K gates, self-resetting
__device__ unsigned g_bar;            // grid barrier counter (reset per launch)

__global__ void reset_kernel() { g_bar = 0u; }

// ---------------- grid barrier (all NBLK blocks co-resident) --------------
__device__ __forceinline__ void grid_sync(unsigned target) {
    __threadfence();
    __syncthreads();
    if (threadIdx.x == 0) {
        atomicAdd(&g_bar, 1u);
        while (*(volatile unsigned*)&g_bar < target) __nanosleep(64);
    }
    __syncthreads();
}

// ---------------- CSR build: warp per row -----------------------------------
__device__ void csr_phase(const float* __restrict__ adj, int gwarp, int lane) {
    for (int r = gwarp; r < N_NODES; r += NWARP) {
        const float4* a = reinterpret_cast<const float4*>(adj + (size_t)r * N_NODES);
        int* outc = g_cols + r * MAXD;
        int base = 0;
        for (int j0 = 0; j0 < N_NODES; j0 += 128) {
            float4 v = a[(j0 >> 2) + lane];
            float vv[4] = {v.x, v.y, v.z, v.w};
            #pragma unroll
            for (int c = 0; c < 4; c++) {
                unsigned m = __ballot_sync(0xffffffffu, vv[c] != 0.0f);
                if (vv[c] != 0.0f) {
                    int pos = base + __popc(m & ((1u << lane) - 1u));
                    if (pos < MAXD) outc[pos] = j0 + lane * 4 + c;
                }
                base += __popc(m);
            }
        }
        if (lane == 0) g_deg[r] = base < MAXD ? base : MAXD;
    }
}

// ---------------- split-K GEMM + gated reduce + el/er proj, per 128-thr half
__device__ void gemm_phase(const float* __restrict__ A, const float* __restrict__ B,
                           const float* __restrict__ al, const float* __restrict__ ar,
                           int H, int half, int ht, float* AsT, float* Bs, int* s_flag) {
    int barid = 1 + half;
    int tx = ht & 15, ty = ht >> 4;
    for (int item = blockIdx.x * 2 + half; item < GEMM_ITEMS; item += NHALF) {
        int rb      = item >> 3;
        int rowBase = rb * BM;
        int k0      = (item & 7) * KS;

        float4 a_n[2], b_n[4];
        #pragma unroll
        for (int s = 0; s < 2; s++) {
            int idx = ht + 128 * s;
            a_n[s] = *reinterpret_cast<const float4*>(
                A + (size_t)(rowBase + (idx >> 3)) * KDIM + k0 + ((idx & 7) << 2));
        }
        #pragma unroll
        for (int s = 0; s < 4; s++) {
            int idx = ht + 128 * s;
            b_n[s] = *reinterpret_cast<const float4*>(
                B + (size_t)(k0 + (idx >> 4)) * 64 + ((idx & 15) << 2));
        }

        ull acc[4][2] = {{0,0},{0,0},{0,0},{0,0}};

        for (int kt = 0; kt < KS; kt += 32) {
            #pragma unroll
            for (int s = 0; s < 2; s++) {
                int idx = ht + 128 * s;
                int row = idx >> 3;
                int kk  = (idx & 7) << 2;
                float av[4] = {a_n[s].x, a_n[s].y, a_n[s].z, a_n[s].w};
                #pragma unroll
                for (int i2 = 0; i2 < 4; i2++) {
                    int k = kk + i2;
                    AsT[k * 36 + (row ^ (((k >> 3) & 3) << 2))] = av[i2];
                }
            }
            #pragma unroll
            for (int s = 0; s < 4; s++) {
                int idx = ht + 128 * s;
                *reinterpret_cast<float4*>(&Bs[(idx >> 4) * 64 + ((idx & 15) << 2)]) = b_n[s];
            }
            HBAR(barid);
            if (kt + 32 < KS) {
                #pragma unroll
                for (int s = 0; s < 2; s++) {
                    int idx = ht + 128 * s;
                    a_n[s] = *reinterpret_cast<const float4*>(
                        A + (size_t)(rowBase + (idx >> 3)) * KDIM + k0 + kt + 32 + ((idx & 7) << 2));
                }
                #pragma unroll
                for (int s = 0; s < 4; s++) {
                    int idx = ht + 128 * s;
                    b_n[s] = *reinterpret_cast<const float4*>(
                        B + (size_t)(k0 + kt + 32 + (idx >> 4)) * 64 + ((idx & 15) << 2));
                }
            }
            #pragma unroll
            for (int k = 0; k < 32; k++) {
                int sr = (ty ^ ((k >> 3) & 3)) << 2;
                float4 av = *reinterpret_cast<const float4*>(&AsT[k * 36 + sr]);
                ulonglong2 bb = *reinterpret_cast<const ulonglong2*>(&Bs[k * 64 + tx * 4]);
                ull pa0 = pack2(av.x), pa1 = pack2(av.y), pa2 = pack2(av.z), pa3 = pack2(av.w);
                fma2(acc[0][0], pa0, bb.x); fma2(acc[0][1], pa0, bb.y);
                fma2(acc[1][0], pa1, bb.x); fma2(acc[1][1], pa1, bb.y);
                fma2(acc[2][0], pa2, bb.x); fma2(acc[2][1], pa2, bb.y);
                fma2(acc[3][0], pa3, bb.x); fma2(acc[3][1], pa3, bb.y);
            }
            HBAR(barid);
        }

        float* P = g_part + (size_t)(item & 7) * (N_NODES * D_H);
        #pragma unroll
        for (int i2 = 0; i2 < 4; i2++) {
            int r = rowBase + ty * 4 + i2;
            ulonglong2 v; v.x = acc[i2][0]; v.y = acc[i2][1];
            *reinterpret_cast<ulonglong2*>(P + (size_t)r * 64 + tx * 4) = v;
        }

        // ---- last-split gate: reduce 8 partials (fixed order) + proj ------
        __threadfence();
        HBAR(barid);
        if (ht == 0) {
            unsigned old = atomicAdd(&g_cnt[rb], 1u);
            int last = (old == KSPLIT - 1);
            if (last) g_cnt[rb] = 0;
            s_flag[half] = last;
        }
        HBAR(barid);
        if (s_flag[half]) {
            float* sC  = Bs;          // 2048 floats
            float* sAl = AsT;         // 512
            float* sAr = AsT + 512;   // 512
            const size_t SZ = (size_t)N_NODES * D_H;
            #pragma unroll
            for (int s = 0; s < 4; s++) {
                int e4 = ht + 128 * s;
                size_t off = (size_t)rowBase * 64 + (size_t)e4 * 4;
                const float4* p = reinterpret_cast<const float4*>(g_part + off);
                float4 v0 = __ldcg(p);
                float4 v1 = __ldcg(p + 1*(SZ/4)), v2 = __ldcg(p + 2*(SZ/4));
                float4 v3 = __ldcg(p + 3*(SZ/4)), v4 = __ldcg(p + 4*(SZ/4));
                float4 v5 = __ldcg(p + 5*(SZ/4)), v6 = __ldcg(p + 6*(SZ/4));
                float4 v7 = __ldcg(p + 7*(SZ/4));
                float4 rr;
                rr.x = ((v0.x+v1.x)+(v2.x+v3.x)) + ((v4.x+v5.x)+(v6.x+v7.x));
                rr.y = ((v0.y+v1.y)+(v2.y+v3.y)) + ((v4.y+v5.y)+(v6.y+v7.y));
                rr.z = ((v0.z+v1.z)+(v2.z+v3.z)) + ((v4.z+v5.z)+(v6.z+v7.z));
                rr.w = ((v0.w+v1.w)+(v2.w+v3.w)) + ((v4.w+v5.w)+(v6.w+v7.w));
                *reinterpret_cast<float4*>(g_x + off) = rr;
                *reinterpret_cast<float4*>(sC + e4 * 4) = rr;
            }
            for (int idx = ht; idx < 64 * H; idx += 128) {
                sAl[idx] = al[idx];
                sAr[idx] = ar[idx];
            }
            HBAR(barid);
            for (int t = ht; t < 32 * H; t += 128) {
                int r = t / H, h = t - r * H;
                float sl = 0.f, sr2 = 0.f;
                #pragma unroll
                for (int d = 0; d < 64; d++) {
                    float cv = sC[r * 64 + d];
                    sl  += cv * sAl[d * H + h];
                    sr2 += cv * sAr[d * H + h];
                }
                g_el[(rowBase + r) * H + h] = sl;
                g_er[(rowBase + r) * H + h] = sr2;
            }
            HBAR(barid);   // protect smem before next item's staging
        }
    }
}

// ---------------- 8-head aggregation: warp per node ------------------------
__device__ void agg8_phase(const float* __restrict__ bias, float* __restrict__ outp,
                           int gwarp, int lane, float* wbase, int* cbase) {
    int h  = lane & 7;
    int qg = lane >> 3;
    const float* xbase = g_x + qg * 16;
    for (int i = gwarp; i < N_NODES; i += NWARP) {
        int deg = g_deg[i];
        const int* cols = g_cols + (size_t)i * MAXD;
        float elh = __ldcg(&g_el[i * HEADS + h]);
        ull acc[8] = {0,0,0,0,0,0,0,0};
        ull sw2 = 0ull;

        for (int j0 = 0; j0 < deg; j0 += CH) {
            int cl = min(CH, deg - j0);
            if (lane < cl)      cbase[lane]      = cols[j0 + lane];
            if (lane + 32 < cl) cbase[lane + 32] = cols[j0 + lane + 32];
            __syncwarp();
            for (int idx = lane; idx < cl * 8; idx += 32) {
                int jj = idx >> 3;
                float s = elh + __ldcg(&g_er[cbase[jj] * HEADS + h]);
                s = (s >= 0.f) ? s : 0.2f * s;
                wbase[jj * 8 + h] = __expf(s);
            }
            __syncwarp();
            #pragma unroll 4
            for (int jj = 0; jj < cl; jj++) {
                ull pw = pack2(wbase[jj * 8 + h]);
                const float* xr = xbase + (size_t)cbase[jj] * D_H;
                ulonglong2 x0 = __ldcg(reinterpret_cast<const ulonglong2*>(xr));
                ulonglong2 x1 = __ldcg(reinterpret_cast<const ulonglong2*>(xr + 4));
                ulonglong2 x2 = __ldcg(reinterpret_cast<const ulonglong2*>(xr + 8));
                ulonglong2 x3 = __ldcg(reinterpret_cast<const ulonglong2*>(xr + 12));
                fma2(acc[0], pw, x0.x); fma2(acc[1], pw, x0.y);
                fma2(acc[2], pw, x1.x); fma2(acc[3], pw, x1.y);
                fma2(acc[4], pw, x2.x); fma2(acc[5], pw, x2.y);
                fma2(acc[6], pw, x3.x); fma2(acc[7], pw, x3.y);
                add2(sw2, pw);
            }
            __syncwarp();
        }

        float sw, dmy;
        unpack2(sw2, sw, dmy);
        float inv = 1.0f / fmaxf(sw, 1e-12f);
        float* o = outp + (size_t)i * (HEADS * D_H) + h * D_H + qg * 16;
        const float* bq = bias + qg * 16;
        #pragma unroll
        for (int t4 = 0; t4 < 4; t4++) {
            float v0, v1, v2, v3;
            unpack2(acc[t4*2],   v0, v1);
            unpack2(acc[t4*2+1], v2, v3);
            v0 = v0 * inv + bq[t4*4+0];
            v1 = v1 * inv + bq[t4*4+1];
            v2 = v2 * inv + bq[t4*4+2];
            v3 = v3 * inv + bq[t4*4+3];
            v0 = (v0 > 0.f) ? v0 : (__expf(v0) - 1.0f);
            v1 = (v1 > 0.f) ? v1 : (__expf(v1) - 1.0f);
            v2 = (v2 > 0.f) ? v2 : (__expf(v2) - 1.0f);
            v3 = (v3 > 0.f) ? v3 : (__expf(v3) - 1.0f);
            *reinterpret_cast<float4*>(o + t4 * 4) = make_float4(v0, v1, v2, v3);
        }
    }
}

// ---------------- 1-head aggregation: warp per node, no activation ---------
__device__ void agg1_phase(const float* __restrict__ bias, float* __restrict__ outp,
                           int gwarp, int lane, float* wbase, int* cbase) {
    for (int i = gwarp; i < N_NODES; i += NWARP) {
        int deg = g_deg[i];
        const int* cols = g_cols + (size_t)i * MAXD;
        float eli = __ldcg(&g_el[i]);
        ull acc = 0ull, sw2 = 0ull;

        for (int j0 = 0; j0 < deg; j0 += CH) {
            int cl = min(CH, deg - j0);
            if (lane < cl) {
                int c = cols[j0 + lane];
                cbase[lane] = c;
                float s = eli + __ldcg(&g_er[c]);
                s = (s >= 0.f) ? s : 0.2f * s;
                wbase[lane] = __expf(s);
            }
            if (lane + 32 < cl) {
                int c = cols[j0 + lane + 32];
                cbase[lane + 32] = c;
                float s = eli + __ldcg(&g_er[c]);
                s = (s >= 0.f) ? s : 0.2f * s;
                wbase[lane + 32] = __expf(s);
            }
            __syncwarp();
            #pragma unroll 8
            for (int jj = 0; jj < cl; jj++) {
                ull pw = pack2(wbase[jj]);
                ull xv = __ldcg(reinterpret_cast<const ull*>(
                    g_x + (size_t)cbase[jj] * D_H + lane * 2));
                fma2(acc, pw, xv);
                add2(sw2, pw);
            }
            __syncwarp();
        }

        float sw, dmy;
        unpack2(sw2, sw, dmy);
        float inv = 1.0f / fmaxf(sw, 1e-12f);
        float v0, v1;
        unpack2(acc, v0, v1);
        v0 = v0 * inv + bias[lane * 2];
        v1 = v1 * inv + bias[lane * 2 + 1];
        *reinterpret_cast<float2*>(outp + (size_t)i * D_H + lane * 2) = make_float2(v0, v1);
    }
}

// ---------------- mega kernel: all 3 layers in one launch -------------------
__global__ __launch_bounds__(256, 2)
void mega_kernel(const float* __restrict__ adj, const float* __restrict__ feat,
                 const float* __restrict__ W0, const float* __restrict__ al0,
                 const float* __restrict__ ar0, const float* __restrict__ b0,
                 const float* __restrict__ W1, const float* __restrict__ al1,
                 const float* __restrict__ ar1, const float* __restrict__ b1,
                 const float* __restrict__ W2, const float* __restrict__ al2,
                 const float* __restrict__ ar2, const float* __restrict__ b2,
                 float* __restrict__ out) {
    __shared__ __align__(16) float s_buf[6400];   // 25.6 KB, aliased per phase
    __shared__ int s_flag[2];

    int tid  = threadIdx.x;
    int half = tid >> 7;
    int ht   = tid & 127;
    int warp = tid >> 5;
    int lane = tid & 31;
    int gwarp = blockIdx.x * 8 + warp;

    float* AsT   = s_buf + half * 3200;   // gemm: [k*36 + r]
    float* Bs    = AsT + 1152;            // gemm: [k*64 + c]
    float* wbase = s_buf + warp * 576;    // agg: weights (512) + cols (64 ints)
    int*   cbase = (int*)(wbase + 512);

    // phase 1: CSR build + layer-0 GEMM (independent; gate does reduce+proj)
    csr_phase(adj, gwarp, lane);
    gemm_phase(feat, W0, al0, ar0, HEADS, half, ht, AsT, Bs, s_flag);
    grid_sync(1u * NBLK);
    agg8_phase(b0, g_h1, gwarp, lane, wbase, cbase);
    grid_sync(2u * NBLK);
    gemm_phase(g_h1, W1, al1, ar1, HEADS, half, ht, AsT, Bs, s_flag);
    grid_sync(3u * NBLK);
    agg8_phase(b1, g_h2, gwarp, lane, wbase, cbase);
    grid_sync(4u * NBLK);
    gemm_phase(g_h2, W2, al2, ar2, 1, half, ht, AsT, Bs, s_flag);
    grid_sync(5u * NBLK);
    agg1_phase(b2, out, gwarp, lane, wbase, cbase);
}

// ---------------- launch ---------------------------------------------------
extern "C" void kernel_launch(void* const* d_in, const int* in_sizes, int n_in,
                              void* d_out, int out_size) {
    const float* adj  = (const float*)d_in[0];
    const float* feat = (const float*)d_in[1];
    const float* W0   = (const float*)d_in[2];
    const float* al0  = (const float*)d_in[3];
    const float* ar0  = (const float*)d_in[4];
    const float* b0   = (const float*)d_in[5];
    const float* W1   = (const float*)d_in[6];
    const float* al1  = (const float*)d_in[7];
    const float* ar1  = (const float*)d_in[8];
    const float* b1   = (const float*)d_in[9];
    const float* W2   = (const float*)d_in[10];
    const float* al2  = (const float*)d_in[11];
    const float* ar2  = (const float*)d_in[12];
    const float* b2   = (const float*)d_in[13];
    float* out = (float*)d_out;

    reset_kernel<<<1, 1>>>();
    mega_kernel<<<NBLK, 256>>>(adj, feat, W0, al0, ar0, b0,
                               W1, al1, ar1, b1,
                               W2, al2, ar2, b2, out);
}

// round 14
// speedup vs baseline: 1.3502x; 1.3502x over previous
#include <cuda_runtime.h>
#include <math.h>

#define N_NODES 4096
#define KDIM    512
#define D_H     64
#define HEADS   8
#define MAXD    192
#define CH      64
#define KSPLIT  16
#define KS      32
#define BM      32
#define ROWBLKS (N_NODES / BM)              // 128
#define GEMM_BLOCKS (ROWBLKS * KSPLIT)      // 2048
#define CSR_BLOCKS  1024

typedef unsigned long long ull;

// ---------------- packed f32x2 helpers (Blackwell) ----------------
__device__ __forceinline__ ull pack2(float a) {
    ull r;
    asm("mov.b64 %0, {%1, %1};" : "=l"(r) : "f"(a));
    return r;
}
__device__ __forceinline__ void fma2(ull& d, ull a, ull b) {
    asm("fma.rn.f32x2 %0, %1, %2, %0;" : "+l"(d) : "l"(a), "l"(b));
}
__device__ __forceinline__ void add2(ull& d, ull a) {
    asm("add.rn.f32x2 %0, %0, %1;" : "+l"(d) : "l"(a));
}
__device__ __forceinline__ void unpack2(ull v, float& lo, float& hi) {
    asm("mov.b64 {%0, %1}, %2;" : "=f"(lo), "=f"(hi) : "l"(v));
}

// ---------------- scratch ----------------
__device__ float g_x [N_NODES * D_H];
__device__ float g_el[N_NODES * HEADS];
__device__ float g_er[N_NODES * HEADS];
__device__ float g_h1[N_NODES * D_H * HEADS];
__device__ float g_h2[N_NODES * D_H * HEADS];
__device__ float g_part[KSPLIT * N_NODES * D_H];   // 16 MB
__device__ int   g_cols[N_NODES * MAXD];
__device__ int   g_deg [N_NODES];

// ---- split-K GEMM (single K-chunk per block) + fused CSR build ------------
// gemm blocks [0, GEMM_BLOCKS): rowblock = bx>>4 (32 rows), split = bx&15 (K=32).
// csr blocks  [GEMM_BLOCKS, ...): 4 warps, warp per adjacency row (layer 0 only).
__global__ __launch_bounds__(128, 8) void gemm_csr_kernel(const float* __restrict__ adj,
                                                          const float* __restrict__ A,
                                                          const float* __restrict__ B) {
    if (blockIdx.x >= GEMM_BLOCKS) {
        int warp = (blockIdx.x - GEMM_BLOCKS) * 4 + (threadIdx.x >> 5);
        int lane = threadIdx.x & 31;
        const float4* a = reinterpret_cast<const float4*>(adj + (size_t)warp * N_NODES);
        int* outc = g_cols + warp * MAXD;
        int base = 0;
        for (int j0 = 0; j0 < N_NODES; j0 += 128) {
            float4 v = a[(j0 >> 2) + lane];
            float vv[4] = {v.x, v.y, v.z, v.w};
            #pragma unroll
            for (int c = 0; c < 4; c++) {
                unsigned m = __ballot_sync(0xffffffffu, vv[c] != 0.0f);
                if (vv[c] != 0.0f) {
                    int pos = base + __popc(m & ((1u << lane) - 1u));
                    if (pos < MAXD) outc[pos] = j0 + lane * 4 + c;
                }
                base += __popc(m);
            }
        }
        if (lane == 0) g_deg[warp] = base < MAXD ? base : MAXD;
        return;
    }

    // ------- GEMM partial: 32 rows x 64 cols, K slice 32, 4x4 micro-tile ---
    __shared__ float AsT[32][36];   // [k][row], row XOR-swizzled in groups of 4
    __shared__ float Bs[32][64];
    int tid = threadIdx.x;
    int tx = tid & 15, ty = tid >> 4;
    int rowBase = (blockIdx.x >> 4) * BM;
    int k0      = (blockIdx.x & 15) * KS;

    // stage A [32 rows x 32 k], transposed + swizzled: 2 float4/thread
    #pragma unroll
    for (int s = 0; s < 2; s++) {
        int idx = tid + 128 * s;
        int row = idx >> 3;
        int kk  = (idx & 7) << 2;
        float4 v = *reinterpret_cast<const float4*>(
            A + (size_t)(rowBase + row) * KDIM + k0 + kk);
        float av[4] = {v.x, v.y, v.z, v.w};
        #pragma unroll
        for (int i = 0; i < 4; i++) {
            int k = kk + i;
            AsT[k][row ^ (((k >> 3) & 3) << 2)] = av[i];
        }
    }
    // stage B [32 k x 64 n]: 4 float4/thread
    #pragma unroll
    for (int s = 0; s < 4; s++) {
        int idx = tid + 128 * s;
        *reinterpret_cast<float4*>(&Bs[idx >> 4][(idx & 15) << 2]) =
            *reinterpret_cast<const float4*>(B + (size_t)(k0 + (idx >> 4)) * 64 + ((idx & 15) << 2));
    }
    __syncthreads();

    ull acc[4][2] = {{0,0},{0,0},{0,0},{0,0}};
    #pragma unroll
    for (int k = 0; k < KS; k++) {
        int sr = (ty ^ ((k >> 3) & 3)) << 2;
        float4 av = *reinterpret_cast<const float4*>(&AsT[k][sr]);
        ulonglong2 bb = *reinterpret_cast<const ulonglong2*>(&Bs[k][tx * 4]);
        ull pa0 = pack2(av.x), pa1 = pack2(av.y), pa2 = pack2(av.z), pa3 = pack2(av.w);
        fma2(acc[0][0], pa0, bb.x); fma2(acc[0][1], pa0, bb.y);
        fma2(acc[1][0], pa1, bb.x); fma2(acc[1][1], pa1, bb.y);
        fma2(acc[2][0], pa2, bb.x); fma2(acc[2][1], pa2, bb.y);
        fma2(acc[3][0], pa3, bb.x); fma2(acc[3][1], pa3, bb.y);
    }

    float* P = g_part + (size_t)(blockIdx.x & 15) * (N_NODES * D_H);
    #pragma unroll
    for (int i = 0; i < 4; i++) {
        int r = rowBase + ty * 4 + i;
        ulonglong2 v; v.x = acc[i][0]; v.y = acc[i][1];
        *reinterpret_cast<ulonglong2*>(P + (size_t)r * 64 + tx * 4) = v;
    }
}

// ---- reduce 16 split-K partials (fixed order) + el/er projection ----------
// 256 blocks x 256 threads; block handles 16 rows; thread handles one float4.
__global__ __launch_bounds__(256) void reduce_proj_kernel(const float* __restrict__ al,
                                                          const float* __restrict__ ar,
                                                          float* __restrict__ X, int H) {
    __shared__ float sC[1024];       // 16 rows x 64
    __shared__ float sAl[512];
    __shared__ float sAr[512];
    int tid = threadIdx.x;
    int rowBase = blockIdx.x * 16;
    size_t off4 = (size_t)rowBase * 16 + tid;          // float4 index in [N*16)
    const float4* p = reinterpret_cast<const float4*>(g_part) + off4;
    const size_t SZ4 = (size_t)N_NODES * 16;           // float4s per partial

    float4 v[16];
    #pragma unroll
    for (int s = 0; s < 16; s++) v[s] = p[s * SZ4];
    #pragma unroll
    for (int st = 8; st >= 1; st >>= 1) {
        #pragma unroll
        for (int s = 0; s < st; s++) {
            v[s].x += v[s + st].x; v[s].y += v[s + st].y;
            v[s].z += v[s + st].z; v[s].w += v[s + st].w;
        }
    }
    reinterpret_cast<float4*>(X)[off4] = v[0];
    *reinterpret_cast<float4*>(&sC[tid * 4]) = v[0];

    for (int idx = tid; idx < 64 * H; idx += 256) {
        sAl[idx] = al[idx];
        sAr[idx] = ar[idx];
    }
    __syncthreads();
    if (tid < 16 * H) {
        int r = (H == 8) ? (tid >> 3) : tid;
        int h = (H == 8) ? (tid & 7)  : 0;
        float sl = 0.f, sr = 0.f;
        #pragma unroll
        for (int d = 0; d < 64; d++) {
            float cv = sC[r * 64 + d];
            sl += cv * sAl[d * H + h];
            sr += cv * sAr[d * H + h];
        }
        g_el[(rowBase + r) * H + h] = sl;
        g_er[(rowBase + r) * H + h] = sr;
    }
}

// ---------------- 8-head aggregation: WARP per node, 4 nodes/block ---------
__global__ __launch_bounds__(128) void agg8_kernel(const float* __restrict__ bias,
                                                   float* __restrict__ out, int act) {
    int w    = threadIdx.x >> 5;
    int lane = threadIdx.x & 31;
    int i    = blockIdx.x * 4 + w;
    int h    = lane & 7;
    int qg   = lane >> 3;

    __shared__ int s_cols[4][CH];
    __shared__ ull s_w[4][CH][HEADS];

    int deg = g_deg[i];
    const int* cols = g_cols + (size_t)i * MAXD;
    float elh = g_el[i * HEADS + h];
    const float* xbase = g_x + qg * 16;

    ull acc[8] = {0,0,0,0,0,0,0,0};
    ull sw2 = 0ull;

    for (int j0 = 0; j0 < deg; j0 += CH) {
        int cl = min(CH, deg - j0);
        if (lane < cl)      s_cols[w][lane]      = cols[j0 + lane];
        if (lane + 32 < cl) s_cols[w][lane + 32] = cols[j0 + lane + 32];
        __syncwarp();
        for (int idx = lane; idx < cl * 8; idx += 32) {
            int jj = idx >> 3;
            float s = elh + g_er[s_cols[w][jj] * HEADS + h];
            s = (s >= 0.f) ? s : 0.2f * s;
            s_w[w][jj][h] = pack2(__expf(s));
        }
        __syncwarp();
        #pragma unroll 2
        for (int jj = 0; jj < cl; jj++) {
            ull pw = s_w[w][jj][h];
            const float* xr = xbase + (size_t)s_cols[w][jj] * D_H;
            ulonglong2 x0 = *reinterpret_cast<const ulonglong2*>(xr);
            ulonglong2 x1 = *reinterpret_cast<const ulonglong2*>(xr + 4);
            ulonglong2 x2 = *reinterpret_cast<const ulonglong2*>(xr + 8);
            ulonglong2 x3 = *reinterpret_cast<const ulonglong2*>(xr + 12);
            fma2(acc[0], pw, x0.x); fma2(acc[1], pw, x0.y);
            fma2(acc[2], pw, x1.x); fma2(acc[3], pw, x1.y);
            fma2(acc[4], pw, x2.x); fma2(acc[5], pw, x2.y);
            fma2(acc[6], pw, x3.x); fma2(acc[7], pw, x3.y);
            add2(sw2, pw);
        }
        __syncwarp();
    }

    float sw, dmy;
    unpack2(sw2, sw, dmy);
    float inv = 1.0f / fmaxf(sw, 1e-12f);
    float* o = out + (size_t)i * (HEADS * D_H) + h * D_H + qg * 16;
    const float* bq = bias + qg * 16;
    #pragma unroll
    for (int t4 = 0; t4 < 4; t4++) {
        float v0, v1, v2, v3;
        unpack2(acc[t4*2],   v0, v1);
        unpack2(acc[t4*2+1], v2, v3);
        v0 = v0 * inv + bq[t4*4+0];
        v1 = v1 * inv + bq[t4*4+1];
        v2 = v2 * inv + bq[t4*4+2];
        v3 = v3 * inv + bq[t4*4+3];
        if (act) {
            v0 = (v0 > 0.f) ? v0 : expm1f(v0);
            v1 = (v1 > 0.f) ? v1 : expm1f(v1);
            v2 = (v2 > 0.f) ? v2 : expm1f(v2);
            v3 = (v3 > 0.f) ? v3 : expm1f(v3);
        }
        *reinterpret_cast<float4*>(o + t4 * 4) = make_float4(v0, v1, v2, v3);
    }
}

// ---------------- 1-head aggregation: WARP per node, 4 nodes/block ---------
__global__ __launch_bounds__(128) void agg1_kernel(const float* __restrict__ bias,
                                                   float* __restrict__ out) {
    int w    = threadIdx.x >> 5;
    int lane = threadIdx.x & 31;
    int i    = blockIdx.x * 4 + w;

    __shared__ int s_cols[4][CH];
    __shared__ ull s_w[4][CH];

    int deg = g_deg[i];
    const int* cols = g_cols + (size_t)i * MAXD;
    float eli = g_el[i];
    const float* xbase = g_x + lane * 2;

    ull acc = 0ull, sw2 = 0ull;

    for (int j0 = 0; j0 < deg; j0 += CH) {
        int cl = min(CH, deg - j0);
        if (lane < cl) {
            int c = cols[j0 + lane];
            s_cols[w][lane] = c;
            float s = eli + g_er[c];
            s = (s >= 0.f) ? s : 0.2f * s;
            s_w[w][lane] = pack2(__expf(s));
        }
        if (lane + 32 < cl) {
            int c = cols[j0 + lane + 32];
            s_cols[w][lane + 32] = c;
            float s = eli + g_er[c];
            s = (s >= 0.f) ? s : 0.2f * s;
            s_w[w][lane + 32] = pack2(__expf(s));
        }
        __syncwarp();
        #pragma unroll 4
        for (int jj = 0; jj < cl; jj++) {
            ull pw = s_w[w][jj];
            ull xv = *reinterpret_cast<const ull*>(xbase + (size_t)s_cols[w][jj] * D_H);
            fma2(acc, pw, xv);
            add2(sw2, pw);
        }
        __syncwarp();
    }

    float sw, dmy;
    unpack2(sw2, sw, dmy);
    float inv = 1.0f / fmaxf(sw, 1e-12f);
    float v0, v1;
    unpack2(acc, v0, v1);
    v0 = v0 * inv + bias[lane * 2];
    v1 = v1 * inv + bias[lane * 2 + 1];
    *reinterpret_cast<float2*>(out + (size_t)i * D_H + lane * 2) = make_float2(v0, v1);
}

// ---------------- launch ---------------------------------------------------
extern "C" void kernel_launch(void* const* d_in, const int* in_sizes, int n_in,
                              void* d_out, int out_size) {
    const float* adj  = (const float*)d_in[0];
    const float* feat = (const float*)d_in[1];
    const float* W0   = (const float*)d_in[2];
    const float* al0  = (const float*)d_in[3];
    const float* ar0  = (const float*)d_in[4];
    const float* b0   = (const float*)d_in[5];
    const float* W1   = (const float*)d_in[6];
    const float* al1  = (const float*)d_in[7];
    const float* ar1  = (const float*)d_in[8];
    const float* b1   = (const float*)d_in[9];
    const float* W2   = (const float*)d_in[10];
    const float* al2  = (const float*)d_in[11];
    const float* ar2  = (const float*)d_in[12];
    const float* b2   = (const float*)d_in[13];
    float* out = (float*)d_out;

    float *x, *h1, *h2;
    cudaGetSymbolAddress((void**)&x,  g_x);
    cudaGetSymbolAddress((void**)&h1, g_h1);
    cudaGetSymbolAddress((void**)&h2, g_h2);

    // layer 0 (CSR build fused into the GEMM launch as extra blocks)
    gemm_csr_kernel<<<GEMM_BLOCKS + CSR_BLOCKS, 128>>>(adj, feat, W0);
    reduce_proj_kernel<<<N_NODES / 16, 256>>>(al0, ar0, x, HEADS);
    agg8_kernel<<<N_NODES / 4, 128>>>(b0, h1, 1);

    // layer 1
    gemm_csr_kernel<<<GEMM_BLOCKS, 128>>>(adj, h1, W1);
    reduce_proj_kernel<<<N_NODES / 16, 256>>>(al1, ar1, x, HEADS);
    agg8_kernel<<<N_NODES / 4, 128>>>(b1, h2, 1);

    // layer 2
    gemm_csr_kernel<<<GEMM_BLOCKS, 128>>>(adj, h2, W2);
    reduce_proj_kernel<<<N_NODES / 16, 256>>>(al2, ar2, x, 1);
    agg1_kernel<<<N_NODES / 4, 128>>>(b2, out);
}